// round 8
// baseline (speedup 1.0000x reference)
#include <cuda_runtime.h>

// Problem constants (fixed by setup_inputs): B=8, H=W=512, D=32, K=64
#define BATCH   8
#define NPIX    (512 * 512)
#define DIM     32
#define KINST   64
#define MARGIN  0.25f

#define NSM     148
#define MAXBPB  148                // supports up to occupancy 8
#define THREADS 128
#define WARPS   (THREADS / 32)     // 4

#define HBPB    32                 // hist blocks per batch
#define HCHUNK  (NPIX / HBPB)      // 8192

// Scratch (__device__ globals: allocs are banned)
__device__ float g_part_sums[MAXBPB * BATCH * KINST * DIM];  // 9.7 MB
__device__ float g_part_cnts[HBPB * BATCH * KINST];          // 64 KB
__device__ float g_sums[BATCH * KINST * DIM];
__device__ float g_counts[BATCH * KINST];

// ---------------------------------------------------------------------------
__global__ void zero_out_kernel(float* __restrict__ out) {
    if (threadIdx.x == 0) out[0] = 0.0f;
}
__global__ void nop_kernel() {}

// ---------------------------------------------------------------------------
// hist: per-block partial label counts (smem atomics, no gmem atomics).
// ---------------------------------------------------------------------------
__global__ __launch_bounds__(256)
void hist_kernel(const int* __restrict__ lab) {
    __shared__ int h[KINST];
    const int b = blockIdx.y;
    for (int i = threadIdx.x; i < KINST; i += 256) h[i] = 0;
    __syncthreads();

    const int4* l4 = (const int4*)(lab + (size_t)b * NPIX + (size_t)blockIdx.x * HCHUNK);
    for (int i = threadIdx.x; i < HCHUNK / 4; i += 256) {
        int4 v = l4[i];
        atomicAdd(&h[v.x], 1);
        atomicAdd(&h[v.y], 1);
        atomicAdd(&h[v.z], 1);
        atomicAdd(&h[v.w], 1);
    }
    __syncthreads();
    for (int i = threadIdx.x; i < KINST; i += 256)
        g_part_cnts[(blockIdx.x * BATCH + b) * KINST + i] = (float)h[i];
}

// ---------------------------------------------------------------------------
// accum: float4-per-thread (8 threads/pixel, 4 pixels per LDG.128), warp-
// private smem bins, double-buffered. Labels fetched once per warp-iter by
// lanes 0..15 and distributed via shfl. Default cached loads (no .cs).
// chunk is a multiple of 64 -> the scalar tail never executes.
// Bin layout rotated by 8*(k&3); physical index (k,d): k*32+((d+8*(k&3))&31).
// ---------------------------------------------------------------------------
#define G 4   // groups per buffer; 1 group = 4 pixels = 1 LDG.128 per thread

__global__ __launch_bounds__(THREADS, 6)
void accum_kernel(const float* __restrict__ emb, const int* __restrict__ lab,
                  int chunk) {
    __shared__ float bins[WARPS][KINST * DIM];   // 32 KB

    const int w    = threadIdx.x >> 5;
    const int lane = threadIdx.x & 31;
    const int sub  = lane & 7;    // thread-in-pixel: dims 4*sub .. 4*sub+3
    const int pix  = lane >> 3;   // pixel-in-group: 0..3
    const int b    = blockIdx.y;

    for (int i = threadIdx.x; i < WARPS * KINST * DIM; i += THREADS)
        (&bins[0][0])[i] = 0.0f;
    __syncthreads();

    const int p0 = blockIdx.x * chunk;
    int p1 = p0 + chunk; if (p1 > NPIX) p1 = NPIX;

    const float*  __restrict__ e  = emb + (size_t)b * NPIX * DIM;
    const float4* __restrict__ e4 = (const float4*)e;
    const int*    __restrict__ l  = lab + (size_t)b * NPIX;

    float* mybin = &bins[w][0];

    const int STEP = WARPS * G * 4;   // 64 pixels per block-iter (16 per warp)

    float4 v[G], v2[G];
    int labreg = 0, labreg2;

    int base = p0;
    if (base + STEP <= p1) {
        // prologue: load first buffer
        if (lane < 16) labreg = l[base + w * 16 + lane];
#pragma unroll
        for (int g = 0; g < G; g++)
            v[g] = e4[(size_t)(base + w * 16 + g * 4 + pix) * 8 + sub];
        base += STEP;

        for (; base + STEP <= p1; base += STEP) {
            // prefetch next buffer (independent of chain below)
            labreg2 = (lane < 16) ? l[base + w * 16 + lane] : 0;
#pragma unroll
            for (int g = 0; g < G; g++)
                v2[g] = e4[(size_t)(base + w * 16 + g * 4 + pix) * 8 + sub];
            // consume current buffer, paired for ILP: 2 LDS, 2 FADD4, 2 STS
#pragma unroll
            for (int gp = 0; gp < G; gp += 2) {
                const int ka = __shfl_sync(0xFFFFFFFFu, labreg, gp * 4 + pix);
                const int kb = __shfl_sync(0xFFFFFFFFu, labreg, gp * 4 + 4 + pix);
                float4* bpa = (float4*)&mybin[(ka << 5) + (((sub << 2) + ((ka & 3) << 3)) & 31)];
                float4* bpb = (float4*)&mybin[(kb << 5) + (((sub << 2) + ((kb & 3) << 3)) & 31)];
                float4 ca = *bpa;
                float4 cb = *bpb;
                ca.x += v[gp].x;     ca.y += v[gp].y;
                ca.z += v[gp].z;     ca.w += v[gp].w;
                cb.x += v[gp + 1].x; cb.y += v[gp + 1].y;
                cb.z += v[gp + 1].z; cb.w += v[gp + 1].w;
                *bpa = ca;
                *bpb = cb;
            }
#pragma unroll
            for (int g = 0; g < G; g++) v[g] = v2[g];
            labreg = labreg2;
        }
        // epilogue: consume last buffer
#pragma unroll
        for (int gp = 0; gp < G; gp += 2) {
            const int ka = __shfl_sync(0xFFFFFFFFu, labreg, gp * 4 + pix);
            const int kb = __shfl_sync(0xFFFFFFFFu, labreg, gp * 4 + 4 + pix);
            float4* bpa = (float4*)&mybin[(ka << 5) + (((sub << 2) + ((ka & 3) << 3)) & 31)];
            float4* bpb = (float4*)&mybin[(kb << 5) + (((sub << 2) + ((kb & 3) << 3)) & 31)];
            float4 ca = *bpa;
            float4 cb = *bpb;
            ca.x += v[gp].x;     ca.y += v[gp].y;
            ca.z += v[gp].z;     ca.w += v[gp].w;
            cb.x += v[gp + 1].x; cb.y += v[gp + 1].y;
            cb.z += v[gp + 1].z; cb.w += v[gp + 1].w;
            *bpa = ca;
            *bpb = cb;
        }
    }
    // scalar tail (never runs when chunk % 64 == 0, kept for safety)
    for (int p = base + w; p < p1; p += WARPS) {
        const float tv = e[(size_t)p * DIM + lane];
        const int   k  = l[p];
        const int  off = (lane + ((k & 3) << 3)) & 31;
        mybin[(k << 5) + off] += tv;
    }
    __syncthreads();

    // fold warp copies (un-rotating), write per-block partials
    float* dst = &g_part_sums[((size_t)blockIdx.x * BATCH + b) * KINST * DIM];
    for (int i = threadIdx.x; i < KINST * DIM; i += THREADS) {
        const int k = i >> 5, d = i & 31;
        const int phys = (k << 5) + ((d + ((k & 3) << 3)) & 31);
        dst[i] = bins[0][phys] + bins[1][phys] + bins[2][phys] + bins[3][phys];
    }
}

// ---------------------------------------------------------------------------
// reduce: fold accum partials (nparts) and hist partials (32).
// 64 blocks * 256 threads = 16384 = B*K*D slots.
// ---------------------------------------------------------------------------
__global__ __launch_bounds__(256)
void reduce_kernel(int nparts) {
    const int i = blockIdx.x * 256 + threadIdx.x;
    float s = 0.0f;
    for (int j = 0; j < nparts; j++)
        s += g_part_sums[(size_t)j * (BATCH * KINST * DIM) + i];
    g_sums[i] = s;

    if (i < BATCH * KINST) {
        float c = 0.0f;
#pragma unroll
        for (int j = 0; j < HBPB; j++)
            c += g_part_cnts[j * (BATCH * KINST) + i];
        g_counts[i] = c;
    }
}

// ---------------------------------------------------------------------------
// finalize: grid = (8 pair-slices, BATCH), centroids in smem (stride 33).
// ---------------------------------------------------------------------------
#define CSTRIDE 33
#define FSLICES 8

__global__ __launch_bounds__(128)
void finalize_kernel(float* __restrict__ out) {
    __shared__ float c[KINST * CSTRIDE];
    __shared__ float cnt[KINST];
    __shared__ float wsum[4];

    const int b   = blockIdx.y;
    const int tid = threadIdx.x;

    for (int i = tid; i < KINST; i += 128)
        cnt[i] = g_counts[b * KINST + i];
    for (int i = tid; i < KINST * DIM; i += 128) {
        const int k = i >> 5, d = i & 31;
        c[k * CSTRIDE + d] = g_sums[b * KINST * DIM + i] / fmaxf(g_counts[b * KINST + k], 1.0f);
    }
    __syncthreads();

    const int t0 = blockIdx.x * (KINST * KINST / FSLICES);
    float acc = 0.0f;
    for (int t = t0 + tid; t < t0 + KINST * KINST / FSLICES; t += 128) {
        const int i = t >> 6, j = t & 63;
        if (j > i && cnt[i] > 0.5f && cnt[j] > 0.5f) {
            float dsum = 0.0f;
#pragma unroll
            for (int d = 0; d < DIM; d++)
                dsum += fabsf(c[i * CSTRIDE + d] - c[j * CSTRIDE + d]);
            const float h = fmaxf(0.0f, MARGIN - dsum);
            acc += h * h;
        }
    }
#pragma unroll
    for (int off = 16; off > 0; off >>= 1)
        acc += __shfl_xor_sync(0xFFFFFFFFu, acc, off);
    if ((tid & 31) == 0) wsum[tid >> 5] = acc;
    __syncthreads();

    if (tid == 0) {
        float n = 0.0f;
#pragma unroll
        for (int k = 0; k < KINST; k++) n += (cnt[k] > 0.5f) ? 1.0f : 0.0f;
        const float ncomp = n * (n - 1.0f) * 0.5f;
        const float part = wsum[0] + wsum[1] + wsum[2] + wsum[3];
        atomicAdd(out, part / (ncomp * (float)BATCH));
    }
}

// ---------------------------------------------------------------------------
extern "C" void kernel_launch(void* const* d_in, const int* in_sizes, int n_in,
                              void* d_out, int out_size) {
    const float* emb = (const float*)d_in[0];
    const int*   lab = (const int*)d_in[1];
    float*       out = (float*)d_out;
    (void)in_sizes; (void)n_in; (void)out_size;

    // Fill the chip at max occupancy; round chunk up to a multiple of 64 so
    // the scalar tail never runs (NPIX = 4096 * 64).
    int occ = 0;
    cudaOccupancyMaxActiveBlocksPerMultiprocessor(&occ, accum_kernel, THREADS, 0);
    if (occ < 1) occ = 1;
    int bpb = (NSM * occ) / BATCH;
    if (bpb < 1)      bpb = 1;
    if (bpb > MAXBPB) bpb = MAXBPB;
    int chunk = (NPIX + bpb - 1) / bpb;
    chunk = (chunk + 63) & ~63;

    zero_out_kernel<<<1, 32>>>(out);                               // launch 0
    hist_kernel<<<dim3(HBPB, BATCH), 256>>>(lab);                  // launch 1
    nop_kernel<<<1, 32>>>();                                       // launch 2
    accum_kernel<<<dim3(bpb, BATCH), THREADS>>>(emb, lab, chunk);  // launch 3 <- profiled
    reduce_kernel<<<64, 256>>>(bpb);                               // launch 4
    finalize_kernel<<<dim3(FSLICES, BATCH), 128>>>(out);           // launch 5
}

// round 9
// speedup vs baseline: 1.1471x; 1.1471x over previous
#include <cuda_runtime.h>
#include <cstdint>

// Problem constants (fixed by setup_inputs): B=8, H=W=512, D=32, K=64
#define BATCH   8
#define NPIX    (512 * 512)
#define DIM     32
#define KINST   64
#define MARGIN  0.25f

#define NSM     148
#define MAXBPB  296
#define THREADS 128
#define WARPS   4

#define HBPB    32                 // hist blocks per batch
#define HCHUNK  (NPIX / HBPB)

// TMA staging
#define NSTG      3
#define SPIX      32               // pixels per stage
#define STG_BYTES (SPIX * DIM * 4) // 4096
#define LAB_BYTES (SPIX * 4)       // 128

// Scratch (__device__ globals: allocs are banned)
__device__ float g_part_sums[MAXBPB * BATCH * KINST * DIM];
__device__ float g_part_cnts[HBPB * BATCH * KINST];
__device__ float g_sums[BATCH * KINST * DIM];
__device__ float g_counts[BATCH * KINST];

// ---------------------------------------------------------------------------
__global__ void nop_kernel() {}

// ---------------------------------------------------------------------------
// hist: per-block partial label counts (smem atomics only).
// ---------------------------------------------------------------------------
__global__ __launch_bounds__(256)
void hist_kernel(const int* __restrict__ lab) {
    __shared__ int h[KINST];
    const int b = blockIdx.y;
    for (int i = threadIdx.x; i < KINST; i += 256) h[i] = 0;
    __syncthreads();

    const int4* l4 = (const int4*)(lab + (size_t)b * NPIX + (size_t)blockIdx.x * HCHUNK);
    for (int i = threadIdx.x; i < HCHUNK / 4; i += 256) {
        int4 v = l4[i];
        atomicAdd(&h[v.x], 1);
        atomicAdd(&h[v.y], 1);
        atomicAdd(&h[v.z], 1);
        atomicAdd(&h[v.w], 1);
    }
    __syncthreads();
    for (int i = threadIdx.x; i < KINST; i += 256)
        g_part_cnts[(blockIdx.x * BATCH + b) * KINST + i] = (float)h[i];
}

// ---------------------------------------------------------------------------
// mbarrier / bulk-copy primitives
// ---------------------------------------------------------------------------
__device__ __forceinline__ uint32_t smem_u32(const void* p) {
    uint32_t a;
    asm("{ .reg .u64 t; cvta.to.shared.u64 t, %1; cvt.u32.u64 %0, t; }"
        : "=r"(a) : "l"(p));
    return a;
}
__device__ __forceinline__ void mbar_init(uint32_t a, uint32_t cnt) {
    asm volatile("mbarrier.init.shared.b64 [%0], %1;" :: "r"(a), "r"(cnt) : "memory");
}
__device__ __forceinline__ void mbar_expect_tx(uint32_t a, uint32_t bytes) {
    asm volatile("mbarrier.arrive.expect_tx.shared.b64 _, [%0], %1;"
                 :: "r"(a), "r"(bytes) : "memory");
}
__device__ __forceinline__ void mbar_arrive(uint32_t a) {
    asm volatile("mbarrier.arrive.shared.b64 _, [%0];" :: "r"(a) : "memory");
}
__device__ __forceinline__ void mbar_wait(uint32_t a, uint32_t ph) {
    asm volatile(
        "{\n\t.reg .pred P;\n"
        "WL%=:\n\t"
        "mbarrier.try_wait.parity.shared.b64 P, [%0], %1;\n\t"
        "@P bra WD%=;\n\t"
        "bra WL%=;\n"
        "WD%=:\n\t}"
        :: "r"(a), "r"(ph) : "memory");
}
__device__ __forceinline__ void bulk_g2s(uint32_t dst, const void* src,
                                         uint32_t bytes, uint32_t mbar) {
    asm volatile(
        "cp.async.bulk.shared::cluster.global.mbarrier::complete_tx::bytes "
        "[%0], [%1], %2, [%3];"
        :: "r"(dst), "l"(src), "r"(bytes), "r"(mbar) : "memory");
}

// ---------------------------------------------------------------------------
// accum: TMA bulk-copy pipeline -> smem stages -> warp-private rotated bins.
// No LDGs in the hot loop; bulk engine keeps ~NSTG*4KB in flight per block
// without consuming the SM's LDG miss slots.
// Bin layout rotated by 8*(k&3); physical index (k,d): k*32+((d+8*(k&3))&31).
// ---------------------------------------------------------------------------
__global__ __launch_bounds__(THREADS)
void accum_kernel(const float* __restrict__ emb, const int* __restrict__ lab,
                  int chunk) {
    __shared__ float  bins[WARPS][KINST * DIM];           // 32 KB
    __shared__ float4 stage[NSTG][SPIX * (DIM / 4)];      // 12 KB
    __shared__ int    slab[NSTG][SPIX];                   // 384 B
    __shared__ __align__(8) unsigned long long mbars[2 * NSTG]; // full[s], empty[s]

    const int tid  = threadIdx.x;
    const int w    = tid >> 5;
    const int lane = tid & 31;
    const int sub  = lane & 7;    // thread-in-pixel: dims 4*sub..4*sub+3
    const int pix  = lane >> 3;   // pixel-in-group 0..3
    const int b    = blockIdx.y;

    for (int i = tid; i < WARPS * KINST * DIM; i += THREADS)
        (&bins[0][0])[i] = 0.0f;

    const uint32_t mb0 = smem_u32(&mbars[0]);
    if (tid == 0) {
#pragma unroll
        for (int s = 0; s < NSTG; s++) {
            mbar_init(mb0 + 8 * s, 1);                // full: producer expect_tx
            mbar_init(mb0 + 8 * (NSTG + s), WARPS);   // empty: 1 arrive per warp
        }
        // ensure mbarrier init is visible to the async (TMA) proxy
        asm volatile("fence.proxy.async.shared::cta;" ::: "memory");
    }
    __syncthreads();

    const int p0 = blockIdx.x * chunk;
    int p1 = p0 + chunk; if (p1 > NPIX) p1 = NPIX;
    const int nst = (p1 - p0) / SPIX;   // all stages full: NPIX, chunk % 32 == 0

    const float* gsrc = emb + ((size_t)b * NPIX + p0) * DIM;
    const int*   lsrc = lab + (size_t)b * NPIX + p0;

    const uint32_t stage0 = smem_u32(&stage[0][0]);
    const uint32_t slab0  = smem_u32(&slab[0][0]);

    // prologue: fill the ring
    if (tid == 0) {
        for (int s = 0; s < NSTG && s < nst; s++) {
            mbar_expect_tx(mb0 + 8 * s, STG_BYTES + LAB_BYTES);
            bulk_g2s(stage0 + s * STG_BYTES, gsrc + (size_t)s * SPIX * DIM,
                     STG_BYTES, mb0 + 8 * s);
            bulk_g2s(slab0 + s * LAB_BYTES, lsrc + s * SPIX,
                     LAB_BYTES, mb0 + 8 * s);
        }
    }

    float* mybin = &bins[w][0];
    uint32_t fph = 0, eph = 0;   // per-slot phase bits
    int s = 0;

    for (int i = 0; i < nst; i++) {
        // wait stage full (acquire)
        mbar_wait(mb0 + 8 * s, (fph >> s) & 1u);
        fph ^= (1u << s);

        // consume: warp w owns pixels w*8 .. w*8+7 of this stage (2 groups)
        const float4* st = &stage[s][0];
        const int*    sl = &slab[s][0];
#pragma unroll
        for (int g = 0; g < 2; g++) {
            const int px = w * 8 + g * 4 + pix;
            const int k  = sl[px];                         // broadcast LDS
            const float4 vv = st[px * 8 + sub];            // LDS.128
            const int off = ((sub << 2) + ((k & 3) << 3)) & 31;
            float4* bp = (float4*)&mybin[(k << 5) + off];
            float4 cur = *bp;
            cur.x += vv.x; cur.y += vv.y; cur.z += vv.z; cur.w += vv.w;
            *bp = cur;
        }
        __syncwarp();
        if (lane == 0) mbar_arrive(mb0 + 8 * (NSTG + s));  // warp done with stage

        // producer refills this slot for stage i+NSTG
        if (tid == 0 && i + NSTG < nst) {
            mbar_wait(mb0 + 8 * (NSTG + s), (eph >> s) & 1u);
            eph ^= (1u << s);
            mbar_expect_tx(mb0 + 8 * s, STG_BYTES + LAB_BYTES);
            bulk_g2s(stage0 + s * STG_BYTES,
                     gsrc + (size_t)(i + NSTG) * SPIX * DIM,
                     STG_BYTES, mb0 + 8 * s);
            bulk_g2s(slab0 + s * LAB_BYTES, lsrc + (i + NSTG) * SPIX,
                     LAB_BYTES, mb0 + 8 * s);
        }
        if (++s == NSTG) s = 0;
    }
    __syncthreads();

    // fold warp copies (un-rotating), write per-block partials
    float* dst = &g_part_sums[((size_t)blockIdx.x * BATCH + b) * KINST * DIM];
    for (int i = tid; i < KINST * DIM; i += THREADS) {
        const int k = i >> 5, d = i & 31;
        const int phys = (k << 5) + ((d + ((k & 3) << 3)) & 31);
        dst[i] = bins[0][phys] + bins[1][phys] + bins[2][phys] + bins[3][phys];
    }
}

// ---------------------------------------------------------------------------
// reduce: fold accum partials (nparts) + hist partials; zero out[0].
// ---------------------------------------------------------------------------
__global__ __launch_bounds__(256)
void reduce_kernel(int nparts, float* __restrict__ out) {
    const int i = blockIdx.x * 256 + threadIdx.x;
    if (i == 0) out[0] = 0.0f;
    float s = 0.0f;
    for (int j = 0; j < nparts; j++)
        s += g_part_sums[(size_t)j * (BATCH * KINST * DIM) + i];
    g_sums[i] = s;

    if (i < BATCH * KINST) {
        float c = 0.0f;
#pragma unroll
        for (int j = 0; j < HBPB; j++)
            c += g_part_cnts[j * (BATCH * KINST) + i];
        g_counts[i] = c;
    }
}

// ---------------------------------------------------------------------------
// finalize: grid = (8 pair-slices, BATCH), centroids in smem (stride 33).
// ---------------------------------------------------------------------------
#define CSTRIDE 33
#define FSLICES 8

__global__ __launch_bounds__(128)
void finalize_kernel(float* __restrict__ out) {
    __shared__ float c[KINST * CSTRIDE];
    __shared__ float cnt[KINST];
    __shared__ float wsum[4];

    const int b   = blockIdx.y;
    const int tid = threadIdx.x;

    for (int i = tid; i < KINST; i += 128)
        cnt[i] = g_counts[b * KINST + i];
    for (int i = tid; i < KINST * DIM; i += 128) {
        const int k = i >> 5, d = i & 31;
        c[k * CSTRIDE + d] = g_sums[b * KINST * DIM + i] / fmaxf(g_counts[b * KINST + k], 1.0f);
    }
    __syncthreads();

    const int t0 = blockIdx.x * (KINST * KINST / FSLICES);
    float acc = 0.0f;
    for (int t = t0 + tid; t < t0 + KINST * KINST / FSLICES; t += 128) {
        const int i = t >> 6, j = t & 63;
        if (j > i && cnt[i] > 0.5f && cnt[j] > 0.5f) {
            float dsum = 0.0f;
#pragma unroll
            for (int d = 0; d < DIM; d++)
                dsum += fabsf(c[i * CSTRIDE + d] - c[j * CSTRIDE + d]);
            const float h = fmaxf(0.0f, MARGIN - dsum);
            acc += h * h;
        }
    }
#pragma unroll
    for (int off = 16; off > 0; off >>= 1)
        acc += __shfl_xor_sync(0xFFFFFFFFu, acc, off);
    if ((tid & 31) == 0) wsum[tid >> 5] = acc;
    __syncthreads();

    if (tid == 0) {
        float n = 0.0f;
#pragma unroll
        for (int k = 0; k < KINST; k++) n += (cnt[k] > 0.5f) ? 1.0f : 0.0f;
        const float ncomp = n * (n - 1.0f) * 0.5f;
        const float part = wsum[0] + wsum[1] + wsum[2] + wsum[3];
        atomicAdd(out, part / (ncomp * (float)BATCH));
    }
}

// ---------------------------------------------------------------------------
extern "C" void kernel_launch(void* const* d_in, const int* in_sizes, int n_in,
                              void* d_out, int out_size) {
    const float* emb = (const float*)d_in[0];
    const int*   lab = (const int*)d_in[1];
    float*       out = (float*)d_out;
    (void)in_sizes; (void)n_in; (void)out_size;

    // Fill the chip; chunk multiple of 32 so every stage is full (NPIX % 32 == 0).
    int occ = 0;
    cudaOccupancyMaxActiveBlocksPerMultiprocessor(&occ, accum_kernel, THREADS, 0);
    if (occ < 1) occ = 1;
    int bpb = (NSM * occ) / BATCH;
    if (bpb < 1)      bpb = 1;
    if (bpb > MAXBPB) bpb = MAXBPB;
    int chunk = (NPIX + bpb - 1) / bpb;
    chunk = (chunk + 31) & ~31;

    hist_kernel<<<dim3(HBPB, BATCH), 256>>>(lab);                  // launch 0
    nop_kernel<<<1, 32>>>();                                       // launch 1
    nop_kernel<<<1, 32>>>();                                       // launch 2
    accum_kernel<<<dim3(bpb, BATCH), THREADS>>>(emb, lab, chunk);  // launch 3 <- profiled
    reduce_kernel<<<64, 256>>>(bpb, out);                          // launch 4
    finalize_kernel<<<dim3(FSLICES, BATCH), 128>>>(out);           // launch 5
}

// round 10
// speedup vs baseline: 1.2182x; 1.0620x over previous
#include <cuda_runtime.h>
#include <cstdint>

// Problem constants (fixed by setup_inputs): B=8, H=W=512, D=32, K=64
#define BATCH   8
#define NPIX    (512 * 512)
#define DIM     32
#define KINST   64
#define MARGIN  0.25f

#define NSM     148
#define MAXBPB  296
#define THREADS 128
#define WARPS   4

#define HBPB    32                 // hist blocks per batch
#define HCHUNK  (NPIX / HBPB)
#define HWARPS  8

// TMA staging
#define NSTG      5
#define SPIX      64                     // pixels per stage
#define STG_BYTES (SPIX * DIM * 4)       // 8192
#define LAB_BYTES (SPIX * 4)             // 256

// dynamic smem layout (16B-aligned sections)
#define OFF_STAGE 0
#define OFF_BINS  (NSTG * STG_BYTES)                      // 40960
#define OFF_SLAB  (OFF_BINS + WARPS * KINST * DIM * 4)    // 73728
#define OFF_MBAR  (OFF_SLAB + NSTG * LAB_BYTES)           // 75008
#define DSMEM     (OFF_MBAR + 2 * NSTG * 8)               // 75088

// Scratch (__device__ globals: allocs are banned)
__device__ float g_part_sums[MAXBPB * BATCH * KINST * DIM];
__device__ float g_part_cnts[HBPB * BATCH * KINST];
__device__ float g_sums[BATCH * KINST * DIM];
__device__ float g_counts[BATCH * KINST];

// ---------------------------------------------------------------------------
__global__ void nop_kernel() {}

// ---------------------------------------------------------------------------
// hist: warp-private smem histograms (intra-warp contention only), then fold.
// ---------------------------------------------------------------------------
__global__ __launch_bounds__(HWARPS * 32)
void hist_kernel(const int* __restrict__ lab) {
    __shared__ int h[HWARPS][KINST];
    const int b   = blockIdx.y;
    const int tid = threadIdx.x;
    const int w   = tid >> 5;
    for (int i = tid; i < HWARPS * KINST; i += HWARPS * 32)
        (&h[0][0])[i] = 0;
    __syncthreads();

    const int4* l4 = (const int4*)(lab + (size_t)b * NPIX + (size_t)blockIdx.x * HCHUNK);
    for (int i = tid; i < HCHUNK / 4; i += HWARPS * 32) {
        int4 v = l4[i];
        atomicAdd(&h[w][v.x], 1);
        atomicAdd(&h[w][v.y], 1);
        atomicAdd(&h[w][v.z], 1);
        atomicAdd(&h[w][v.w], 1);
    }
    __syncthreads();
    for (int i = tid; i < KINST; i += HWARPS * 32) {
        int s = 0;
#pragma unroll
        for (int ww = 0; ww < HWARPS; ww++) s += h[ww][i];
        g_part_cnts[(blockIdx.x * BATCH + b) * KINST + i] = (float)s;
    }
}

// ---------------------------------------------------------------------------
// mbarrier / bulk-copy primitives
// ---------------------------------------------------------------------------
__device__ __forceinline__ uint32_t smem_u32(const void* p) {
    uint32_t a;
    asm("{ .reg .u64 t; cvta.to.shared.u64 t, %1; cvt.u32.u64 %0, t; }"
        : "=r"(a) : "l"(p));
    return a;
}
__device__ __forceinline__ void mbar_init(uint32_t a, uint32_t cnt) {
    asm volatile("mbarrier.init.shared.b64 [%0], %1;" :: "r"(a), "r"(cnt) : "memory");
}
__device__ __forceinline__ void mbar_expect_tx(uint32_t a, uint32_t bytes) {
    asm volatile("mbarrier.arrive.expect_tx.shared.b64 _, [%0], %1;"
                 :: "r"(a), "r"(bytes) : "memory");
}
__device__ __forceinline__ void mbar_arrive(uint32_t a) {
    asm volatile("mbarrier.arrive.shared.b64 _, [%0];" :: "r"(a) : "memory");
}
__device__ __forceinline__ void mbar_wait(uint32_t a, uint32_t ph) {
    asm volatile(
        "{\n\t.reg .pred P;\n"
        "WL%=:\n\t"
        "mbarrier.try_wait.parity.shared.b64 P, [%0], %1;\n\t"
        "@P bra WD%=;\n\t"
        "bra WL%=;\n"
        "WD%=:\n\t}"
        :: "r"(a), "r"(ph) : "memory");
}
__device__ __forceinline__ void bulk_g2s(uint32_t dst, const void* src,
                                         uint32_t bytes, uint32_t mbar) {
    asm volatile(
        "cp.async.bulk.shared::cluster.global.mbarrier::complete_tx::bytes "
        "[%0], [%1], %2, [%3];"
        :: "r"(dst), "l"(src), "r"(bytes), "r"(mbar) : "memory");
}

// ---------------------------------------------------------------------------
// accum: bulk-copy pipeline (5 x 8KB stages) -> smem -> warp-private rotated
// bins. No LDGs in the hot loop. 64-pixel stages = half the sync ops/byte of
// the previous version.
// Bin layout rotated by 8*(k&3); physical index (k,d): k*32+((d+8*(k&3))&31).
// ---------------------------------------------------------------------------
__global__ __launch_bounds__(THREADS)
void accum_kernel(const float* __restrict__ emb, const int* __restrict__ lab,
                  int chunk) {
    extern __shared__ __align__(16) char dsm[];
    float4* stage = (float4*)(dsm + OFF_STAGE);
    float*  bins  = (float*)(dsm + OFF_BINS);
    int*    slab  = (int*)(dsm + OFF_SLAB);

    const int tid  = threadIdx.x;
    const int w    = tid >> 5;
    const int lane = tid & 31;
    const int sub  = lane & 7;    // thread-in-pixel: dims 4*sub..4*sub+3
    const int pix  = lane >> 3;   // pixel-in-group 0..3
    const int b    = blockIdx.y;

    for (int i = tid; i < WARPS * KINST * DIM; i += THREADS)
        bins[i] = 0.0f;

    const uint32_t mb0 = smem_u32(dsm + OFF_MBAR);
    if (tid == 0) {
#pragma unroll
        for (int s = 0; s < NSTG; s++) {
            mbar_init(mb0 + 8 * s, 1);                // full: producer expect_tx
            mbar_init(mb0 + 8 * (NSTG + s), WARPS);   // empty: 1 arrive per warp
        }
        asm volatile("fence.proxy.async.shared::cta;" ::: "memory");
    }
    __syncthreads();

    const int p0 = blockIdx.x * chunk;
    int p1 = p0 + chunk; if (p1 > NPIX) p1 = NPIX;
    if (p1 <= p0) return;
    const int nst = (p1 - p0) / SPIX;   // chunk % 64 == 0, NPIX % 64 == 0

    const float* gsrc = emb + ((size_t)b * NPIX + p0) * DIM;
    const int*   lsrc = lab + (size_t)b * NPIX + p0;

    const uint32_t stage0 = smem_u32(stage);
    const uint32_t slab0  = smem_u32(slab);

    // prologue: fill the ring
    if (tid == 0) {
        for (int s = 0; s < NSTG && s < nst; s++) {
            mbar_expect_tx(mb0 + 8 * s, STG_BYTES + LAB_BYTES);
            bulk_g2s(stage0 + s * STG_BYTES, gsrc + (size_t)s * SPIX * DIM,
                     STG_BYTES, mb0 + 8 * s);
            bulk_g2s(slab0 + s * LAB_BYTES, lsrc + s * SPIX,
                     LAB_BYTES, mb0 + 8 * s);
        }
    }

    float* mybin = bins + w * (KINST * DIM);
    uint32_t fph = 0, eph = 0;   // per-slot phase bits
    int s = 0;

    for (int i = 0; i < nst; i++) {
        mbar_wait(mb0 + 8 * s, (fph >> s) & 1u);
        fph ^= (1u << s);

        // warp w owns pixels w*16 .. w*16+15 of this stage (4 groups of 4)
        const float4* st = &stage[(size_t)s * SPIX * 8];
        const int*    sl = &slab[s * SPIX];
#pragma unroll
        for (int g = 0; g < 4; g++) {
            const int px = w * 16 + g * 4 + pix;
            const int k  = sl[px];                     // broadcast LDS
            const float4 vv = st[px * 8 + sub];        // LDS.128, conflict-free
            const int off = ((sub << 2) + ((k & 3) << 3)) & 31;
            float4* bp = (float4*)&mybin[(k << 5) + off];
            float4 cur = *bp;
            cur.x += vv.x; cur.y += vv.y; cur.z += vv.z; cur.w += vv.w;
            *bp = cur;
        }
        __syncwarp();
        if (lane == 0) mbar_arrive(mb0 + 8 * (NSTG + s));

        // producer refills this slot for stage i+NSTG
        if (tid == 0 && i + NSTG < nst) {
            mbar_wait(mb0 + 8 * (NSTG + s), (eph >> s) & 1u);
            eph ^= (1u << s);
            mbar_expect_tx(mb0 + 8 * s, STG_BYTES + LAB_BYTES);
            bulk_g2s(stage0 + s * STG_BYTES,
                     gsrc + (size_t)(i + NSTG) * SPIX * DIM,
                     STG_BYTES, mb0 + 8 * s);
            bulk_g2s(slab0 + s * LAB_BYTES, lsrc + (i + NSTG) * SPIX,
                     LAB_BYTES, mb0 + 8 * s);
        }
        if (++s == NSTG) s = 0;
    }
    __syncthreads();

    // fold warp copies (un-rotating), write per-block partials
    float* dst = &g_part_sums[((size_t)blockIdx.x * BATCH + b) * KINST * DIM];
    for (int i = tid; i < KINST * DIM; i += THREADS) {
        const int k = i >> 5, d = i & 31;
        const int phys = (k << 5) + ((d + ((k & 3) << 3)) & 31);
        dst[i] = bins[0 * KINST * DIM + phys] + bins[1 * KINST * DIM + phys]
               + bins[2 * KINST * DIM + phys] + bins[3 * KINST * DIM + phys];
    }
}

// ---------------------------------------------------------------------------
// reduce: fold accum partials (nparts) + hist partials; zero out[0].
// ---------------------------------------------------------------------------
__global__ __launch_bounds__(256)
void reduce_kernel(int nparts, float* __restrict__ out) {
    const int i = blockIdx.x * 256 + threadIdx.x;
    if (i == 0) out[0] = 0.0f;
    float s = 0.0f;
    for (int j = 0; j < nparts; j++)
        s += g_part_sums[(size_t)j * (BATCH * KINST * DIM) + i];
    g_sums[i] = s;

    if (i < BATCH * KINST) {
        float c = 0.0f;
#pragma unroll
        for (int j = 0; j < HBPB; j++)
            c += g_part_cnts[j * (BATCH * KINST) + i];
        g_counts[i] = c;
    }
}

// ---------------------------------------------------------------------------
// finalize: grid = (8 pair-slices, BATCH), centroids in smem (stride 33).
// ---------------------------------------------------------------------------
#define CSTRIDE 33
#define FSLICES 8

__global__ __launch_bounds__(128)
void finalize_kernel(float* __restrict__ out) {
    __shared__ float c[KINST * CSTRIDE];
    __shared__ float cnt[KINST];
    __shared__ float wsum[4];

    const int b   = blockIdx.y;
    const int tid = threadIdx.x;

    for (int i = tid; i < KINST; i += 128)
        cnt[i] = g_counts[b * KINST + i];
    for (int i = tid; i < KINST * DIM; i += 128) {
        const int k = i >> 5, d = i & 31;
        c[k * CSTRIDE + d] = g_sums[b * KINST * DIM + i] / fmaxf(g_counts[b * KINST + k], 1.0f);
    }
    __syncthreads();

    const int t0 = blockIdx.x * (KINST * KINST / FSLICES);
    float acc = 0.0f;
    for (int t = t0 + tid; t < t0 + KINST * KINST / FSLICES; t += 128) {
        const int i = t >> 6, j = t & 63;
        if (j > i && cnt[i] > 0.5f && cnt[j] > 0.5f) {
            float dsum = 0.0f;
#pragma unroll
            for (int d = 0; d < DIM; d++)
                dsum += fabsf(c[i * CSTRIDE + d] - c[j * CSTRIDE + d]);
            const float h = fmaxf(0.0f, MARGIN - dsum);
            acc += h * h;
        }
    }
#pragma unroll
    for (int off = 16; off > 0; off >>= 1)
        acc += __shfl_xor_sync(0xFFFFFFFFu, acc, off);
    if ((tid & 31) == 0) wsum[tid >> 5] = acc;
    __syncthreads();

    if (tid == 0) {
        float n = 0.0f;
#pragma unroll
        for (int k = 0; k < KINST; k++) n += (cnt[k] > 0.5f) ? 1.0f : 0.0f;
        const float ncomp = n * (n - 1.0f) * 0.5f;
        const float part = wsum[0] + wsum[1] + wsum[2] + wsum[3];
        atomicAdd(out, part / (ncomp * (float)BATCH));
    }
}

// ---------------------------------------------------------------------------
extern "C" void kernel_launch(void* const* d_in, const int* in_sizes, int n_in,
                              void* d_out, int out_size) {
    const float* emb = (const float*)d_in[0];
    const int*   lab = (const int*)d_in[1];
    float*       out = (float*)d_out;
    (void)in_sizes; (void)n_in; (void)out_size;

    // Opt in to >48KB dynamic smem, then size the grid to fill the chip.
    cudaFuncSetAttribute(accum_kernel,
                         cudaFuncAttributeMaxDynamicSharedMemorySize, DSMEM);
    int occ = 0;
    cudaOccupancyMaxActiveBlocksPerMultiprocessor(&occ, accum_kernel, THREADS, DSMEM);
    if (occ < 1) occ = 1;
    int bpb = (NSM * occ) / BATCH;
    if (bpb < 1)      bpb = 1;
    if (bpb > MAXBPB) bpb = MAXBPB;
    int chunk = (NPIX + bpb - 1) / bpb;
    chunk = (chunk + SPIX - 1) & ~(SPIX - 1);   // full stages only

    hist_kernel<<<dim3(HBPB, BATCH), HWARPS * 32>>>(lab);              // launch 0
    nop_kernel<<<1, 32>>>();                                           // launch 1
    nop_kernel<<<1, 32>>>();                                           // launch 2
    accum_kernel<<<dim3(bpb, BATCH), THREADS, DSMEM>>>(emb, lab, chunk); // launch 3 <- profiled
    reduce_kernel<<<64, 256>>>(bpb, out);                              // launch 4
    finalize_kernel<<<dim3(FSLICES, BATCH), 128>>>(out);               // launch 5
}